// round 1
// baseline (speedup 1.0000x reference)
#include <cuda_runtime.h>
#include <cstdint>
#include <cstddef>

#define NN 100000
#define EE 500000

// Precomputed per-node first-layer tables.
// P[n, 0:128]   = z_pnode[n] @ w1_top      P[n, 128:256] = z_pnode[n] @ w1_bot
// O[n, 0:128]   = z_onode[n] @ w1_top      O[n, 128:256] = z_onode[n] @ w1_bot
__device__ float g_P[(size_t)NN * 256];
__device__ float g_O[(size_t)NN * 256];

// ---------------------------------------------------------------------------
// GEMM: rows 0..99999 -> z_pnode -> g_P ; rows 100000..199999 -> z_onode -> g_O
// blockIdx.x : 64-row tile (200000/64 = 3125)
// blockIdx.y : column half (0 -> w1_top cols, 1 -> w1_bot cols)
// ---------------------------------------------------------------------------
__global__ void __launch_bounds__(256, 2) gemm_kernel(
    const float* __restrict__ zp, const float* __restrict__ zo,
    const float* __restrict__ w1) {
  extern __shared__ float sm[];
  float* ws = sm;               // [128][128]  weight tile
  float* zs = sm + 128 * 128;   // [64][132]   z tile (padded stride)
  const int ZLD = 132;
  const int tid = threadIdx.x;
  const int cb = blockIdx.y;
  const int row0 = blockIdx.x * 64;

  // Load weight tile: cb=0 -> w1 rows 0..127 (top), cb=1 -> rows 128..255 (bot)
  {
    const float4* w4 = (const float4*)(w1 + cb * (128 * 128));
    float4* ws4 = (float4*)ws;
#pragma unroll
    for (int i = 0; i < 16; i++) ws4[tid + 256 * i] = w4[tid + 256 * i];
  }
  // Load z tile (64 rows x 128 cols); rows may straddle the pnode/onode split.
#pragma unroll
  for (int i = 0; i < 8; i++) {
    int slot = tid + 256 * i;
    int r = slot >> 5;
    int c4 = slot & 31;
    int grow = row0 + r;
    const float* src = (grow < NN) ? (zp + (size_t)grow * 128)
                                   : (zo + (size_t)(grow - NN) * 128);
    float4 v = ((const float4*)src)[c4];
    float* dst = zs + r * ZLD + c4 * 4;
    dst[0] = v.x; dst[1] = v.y; dst[2] = v.z; dst[3] = v.w;
  }
  __syncthreads();

  const int cg = tid & 15;   // column group: cols cg*8 .. cg*8+7
  const int rg = tid >> 4;   // row group:    rows rg*4 .. rg*4+3
  float acc[4][8];
#pragma unroll
  for (int i = 0; i < 4; i++)
#pragma unroll
    for (int j = 0; j < 8; j++) acc[i][j] = 0.f;

#pragma unroll 4
  for (int k = 0; k < 128; k++) {
    float zf[4];
#pragma unroll
    for (int i = 0; i < 4; i++) zf[i] = zs[(rg * 4 + i) * ZLD + k];
    float4 wa = *(const float4*)(ws + k * 128 + cg * 8);
    float4 wb = *(const float4*)(ws + k * 128 + cg * 8 + 4);
    float wf[8] = {wa.x, wa.y, wa.z, wa.w, wb.x, wb.y, wb.z, wb.w};
#pragma unroll
    for (int i = 0; i < 4; i++)
#pragma unroll
      for (int j = 0; j < 8; j++) acc[i][j] += zf[i] * wf[j];
  }

#pragma unroll
  for (int i = 0; i < 4; i++) {
    int grow = row0 + rg * 4 + i;
    float* orow = (grow < NN) ? (g_P + (size_t)grow * 256)
                              : (g_O + (size_t)(grow - NN) * 256);
    float* o = orow + cb * 128 + cg * 8;
    float4 v0 = make_float4(acc[i][0], acc[i][1], acc[i][2], acc[i][3]);
    float4 v1 = make_float4(acc[i][4], acc[i][5], acc[i][6], acc[i][7]);
    *(float4*)o = v0;
    *(float4*)(o + 4) = v1;
  }
}

// ---------------------------------------------------------------------------
// Edge pass: one warp per edge.
// out[e] = relu(tabS[src, 0:128] + tabD[dst, 128:256] + b1) . w2 + b2
// ---------------------------------------------------------------------------
__global__ void __launch_bounds__(256) edge_kernel(
    const int* __restrict__ e0, const int* __restrict__ e1,
    const int* __restrict__ e2, const float* __restrict__ b1,
    const float* __restrict__ w2, const float* __restrict__ b2,
    float* __restrict__ out) {
  int gw = (int)((blockIdx.x * 256 + threadIdx.x) >> 5);
  int lane = threadIdx.x & 31;
  if (gw >= 3 * EE) return;
  int t = gw / EE;
  int e = gw - t * EE;
  const int* idx = (t == 0) ? e0 : (t == 1) ? e1 : e2;
  int s = idx[e];
  int d = idx[EE + e];
  const float* srow;
  const float* drow;
  if (t == 0) {        // ptnp: pnode src (top), onode dst (bot)
    srow = g_P + (size_t)s * 256;
    drow = g_O + (size_t)d * 256 + 128;
  } else if (t == 1) { // nptp: onode src (top), pnode dst (bot)
    srow = g_O + (size_t)s * 256;
    drow = g_P + (size_t)d * 256 + 128;
  } else {             // nptnp: onode src (top), onode dst (bot)
    srow = g_O + (size_t)s * 256;
    drow = g_O + (size_t)d * 256 + 128;
  }
  float4 a  = ((const float4*)srow)[lane];
  float4 bv = ((const float4*)drow)[lane];
  float4 bb = ((const float4*)b1)[lane];
  float4 ww = ((const float4*)w2)[lane];
  float h0 = fmaxf(a.x + bv.x + bb.x, 0.f);
  float h1 = fmaxf(a.y + bv.y + bb.y, 0.f);
  float h2 = fmaxf(a.z + bv.z + bb.z, 0.f);
  float h3 = fmaxf(a.w + bv.w + bb.w, 0.f);
  float acc = h0 * ww.x + h1 * ww.y + h2 * ww.z + h3 * ww.w;
#pragma unroll
  for (int o = 16; o; o >>= 1) acc += __shfl_xor_sync(0xffffffffu, acc, o);
  if (lane == 0) out[gw] = acc + b2[0];
}

extern "C" void kernel_launch(void* const* d_in, const int* in_sizes, int n_in,
                              void* d_out, int out_size) {
  const float* zp = (const float*)d_in[0];
  const float* zo = (const float*)d_in[1];
  const int* e0 = (const int*)d_in[2];
  const int* e1 = (const int*)d_in[3];
  const int* e2 = (const int*)d_in[4];
  const float* w1 = (const float*)d_in[5];
  const float* b1 = (const float*)d_in[6];
  const float* w2 = (const float*)d_in[7];
  const float* b2 = (const float*)d_in[8];

  const int smem = (128 * 128 + 64 * 132) * 4;  // 99328 B
  cudaFuncSetAttribute(gemm_kernel,
                       cudaFuncAttributeMaxDynamicSharedMemorySize, smem);
  dim3 g(200000 / 64, 2);
  gemm_kernel<<<g, 256, smem>>>(zp, zo, w1);

  int nwarps = 3 * EE;                     // 1.5M edges, 1 warp each
  int nblocks = (nwarps * 32 + 255) / 256; // 187500
  edge_kernel<<<nblocks, 256>>>(e0, e1, e2, b1, w2, b2, (float*)d_out);
}

// round 3
// speedup vs baseline: 2.0063x; 2.0063x over previous
#include <cuda_runtime.h>
#include <cuda_fp16.h>
#include <cstdint>
#include <cstddef>

#define NN 100000
#define EE 500000

// Per-node first-layer tables in fp16 (102.4 MB total -> L2-resident).
// P[n, 0:128] = z_pnode[n] @ w1_top ; P[n, 128:256] = z_pnode[n] @ w1_bot
__device__ __half g_P[(size_t)NN * 256];
__device__ __half g_O[(size_t)NN * 256];

__device__ __forceinline__ uint32_t f2tf32(float f) {
  uint32_t r;
  asm("cvt.rna.tf32.f32 %0, %1;" : "=r"(r) : "f"(f));
  return r;
}

__device__ __forceinline__ void mma_tf32(float* d, const uint32_t* a,
                                         const uint32_t* b) {
  asm volatile(
      "mma.sync.aligned.m16n8k8.row.col.f32.tf32.tf32.f32 "
      "{%0,%1,%2,%3}, {%4,%5,%6,%7}, {%8,%9}, {%0,%1,%2,%3};"
      : "+f"(d[0]), "+f"(d[1]), "+f"(d[2]), "+f"(d[3])
      : "r"(a[0]), "r"(a[1]), "r"(a[2]), "r"(a[3]), "r"(b[0]), "r"(b[1]));
}

#define AS_LD 132  // stride%32==4 -> conflict-free A frag loads
#define BS_LD 264  // stride%32==8 -> conflict-free B frag loads

// ---------------------------------------------------------------------------
// tf32 tensor-core GEMM: C[200000, 256] = Z[200000,128] @ [w1_top | w1_bot]
// One CTA: 128 rows x 256 cols, K=128. 8 warps, each 64x64.
// ---------------------------------------------------------------------------
__global__ void __launch_bounds__(256, 1) gemm_kernel(
    const float* __restrict__ zp, const float* __restrict__ zo,
    const float* __restrict__ w1) {
  extern __shared__ float sm[];
  float* As = sm;                // [128][AS_LD]
  float* Bs = sm + 128 * AS_LD;  // [128][BS_LD]  Bs[k][nn], nn in [0,256)
  const int tid = threadIdx.x;
  const int row0 = blockIdx.x * 128;

  // Load w1 (256 rows x 128 cols) -> Bs[k][nn]:
  //   w1 row r<128  (top): Bs[r][c]        (k=r,     nn=c)
  //   w1 row r>=128 (bot): Bs[r-128][128+c] (k=r-128, nn=128+c)
  {
    const float4* w4 = (const float4*)w1;
#pragma unroll
    for (int i = 0; i < 32; i++) {
      int slot = tid + 256 * i;  // 8192 float4 slots (256 rows x 32 float4)
      int r = slot >> 5;         // w1 row 0..255
      int c4 = slot & 31;        // float4 within row, 0..31
      float4 v = w4[slot];
      float* dst = Bs + (r & 127) * BS_LD + (r >> 7) * 128 + c4 * 4;
      dst[0] = __uint_as_float(f2tf32(v.x));
      dst[1] = __uint_as_float(f2tf32(v.y));
      dst[2] = __uint_as_float(f2tf32(v.z));
      dst[3] = __uint_as_float(f2tf32(v.w));
    }
  }
  // Load A tile (128 rows x 128 k) with p/o straddle, clamped last tile.
#pragma unroll
  for (int i = 0; i < 16; i++) {
    int slot = tid + 256 * i;  // 4096 float4 slots
    int r = slot >> 5;
    int c4 = slot & 31;
    int grow = row0 + r;
    if (grow > 199999) grow = 199999;
    const float* src = (grow < NN) ? (zp + (size_t)grow * 128)
                                   : (zo + (size_t)(grow - NN) * 128);
    float4 v = ((const float4*)src)[c4];
    float* dst = As + r * AS_LD + c4 * 4;
    dst[0] = __uint_as_float(f2tf32(v.x));
    dst[1] = __uint_as_float(f2tf32(v.y));
    dst[2] = __uint_as_float(f2tf32(v.z));
    dst[3] = __uint_as_float(f2tf32(v.w));
  }
  __syncthreads();

  const int lane = tid & 31;
  const int wid = tid >> 5;
  const int g = lane >> 2;  // group id (0..7)
  const int tg = lane & 3;  // thread in group (0..3)
  const int wm = wid & 1;   // warp M (2)
  const int wn = wid >> 1;  // warp N (4)
  const int arow = wm * 64;
  const int bcol = wn * 64;

  float acc[4][8][4];
#pragma unroll
  for (int mi = 0; mi < 4; mi++)
#pragma unroll
    for (int ni = 0; ni < 8; ni++)
#pragma unroll
      for (int q = 0; q < 4; q++) acc[mi][ni][q] = 0.f;

#pragma unroll
  for (int k0 = 0; k0 < 128; k0 += 8) {
    uint32_t bf[8][2];
#pragma unroll
    for (int ni = 0; ni < 8; ni++) {
      int col = bcol + ni * 8 + g;
      bf[ni][0] = __float_as_uint(Bs[(k0 + tg) * BS_LD + col]);
      bf[ni][1] = __float_as_uint(Bs[(k0 + 4 + tg) * BS_LD + col]);
    }
#pragma unroll
    for (int mi = 0; mi < 4; mi++) {
      int rb = arow + mi * 16 + g;
      uint32_t af[4];
      af[0] = __float_as_uint(As[rb * AS_LD + k0 + tg]);
      af[1] = __float_as_uint(As[(rb + 8) * AS_LD + k0 + tg]);
      af[2] = __float_as_uint(As[rb * AS_LD + k0 + 4 + tg]);
      af[3] = __float_as_uint(As[(rb + 8) * AS_LD + k0 + 4 + tg]);
#pragma unroll
      for (int ni = 0; ni < 8; ni++) mma_tf32(acc[mi][ni], af, bf[ni]);
    }
  }

  // Store C as fp16 table rows. c-frag: (row g | g+8, cols tg*2, tg*2+1).
#pragma unroll
  for (int mi = 0; mi < 4; mi++) {
    int r0 = row0 + wm * 64 + mi * 16 + g;
#pragma unroll
    for (int half = 0; half < 2; half++) {
      int grow = r0 + half * 8;
      if (grow >= 200000) continue;
      __half* tab = (grow < NN) ? (g_P + (size_t)grow * 256)
                                : (g_O + (size_t)(grow - NN) * 256);
#pragma unroll
      for (int ni = 0; ni < 8; ni++) {
        int c = bcol + ni * 8 + tg * 2;
        __half2 hv = __floats2half2_rn(acc[mi][ni][half * 2],
                                       acc[mi][ni][half * 2 + 1]);
        *(__half2*)(tab + c) = hv;
      }
    }
  }
}

// ---------------------------------------------------------------------------
// Edge pass: one warp per edge, fp16 tables.
// out[e] = relu(tabS[src, 0:128] + tabD[dst, 128:256] + b1) . w2 + b2
// ---------------------------------------------------------------------------
__global__ void __launch_bounds__(256) edge_kernel(
    const int* __restrict__ e0, const int* __restrict__ e1,
    const int* __restrict__ e2, const float* __restrict__ b1,
    const float* __restrict__ w2, const float* __restrict__ b2,
    float* __restrict__ out) {
  int gw = (int)((blockIdx.x * 256 + threadIdx.x) >> 5);
  int lane = threadIdx.x & 31;
  if (gw >= 3 * EE) return;
  int t = gw / EE;
  int e = gw - t * EE;
  const int* idx = (t == 0) ? e0 : (t == 1) ? e1 : e2;
  int s = idx[e];
  int d = idx[EE + e];
  const __half* srow;
  const __half* drow;
  if (t == 0) {         // ptnp: pnode src (top), onode dst (bot)
    srow = g_P + (size_t)s * 256;
    drow = g_O + (size_t)d * 256 + 128;
  } else if (t == 1) {  // nptp: onode src (top), pnode dst (bot)
    srow = g_O + (size_t)s * 256;
    drow = g_P + (size_t)d * 256 + 128;
  } else {              // nptnp: onode src (top), onode dst (bot)
    srow = g_O + (size_t)s * 256;
    drow = g_O + (size_t)d * 256 + 128;
  }
  // Each lane handles 4 features: cols lane*4 .. lane*4+3
  uint2 sa = ((const uint2*)srow)[lane];
  uint2 da = ((const uint2*)drow)[lane];
  float2 s01 = __half22float2(*(const __half2*)&sa.x);
  float2 s23 = __half22float2(*(const __half2*)&sa.y);
  float2 d01 = __half22float2(*(const __half2*)&da.x);
  float2 d23 = __half22float2(*(const __half2*)&da.y);
  float4 bb = ((const float4*)b1)[lane];
  float4 ww = ((const float4*)w2)[lane];
  float h0 = fmaxf(s01.x + d01.x + bb.x, 0.f);
  float h1 = fmaxf(s01.y + d01.y + bb.y, 0.f);
  float h2 = fmaxf(s23.x + d23.x + bb.z, 0.f);
  float h3 = fmaxf(s23.y + d23.y + bb.w, 0.f);
  float acc = h0 * ww.x + h1 * ww.y + h2 * ww.z + h3 * ww.w;
#pragma unroll
  for (int o = 16; o; o >>= 1) acc += __shfl_xor_sync(0xffffffffu, acc, o);
  if (lane == 0) out[gw] = acc + b2[0];
}

extern "C" void kernel_launch(void* const* d_in, const int* in_sizes, int n_in,
                              void* d_out, int out_size) {
  const float* zp = (const float*)d_in[0];
  const float* zo = (const float*)d_in[1];
  const int* e0 = (const int*)d_in[2];
  const int* e1 = (const int*)d_in[3];
  const int* e2 = (const int*)d_in[4];
  const float* w1 = (const float*)d_in[5];
  const float* b1 = (const float*)d_in[6];
  const float* w2 = (const float*)d_in[7];
  const float* b2 = (const float*)d_in[8];

  const int smem = (128 * AS_LD + 128 * BS_LD) * 4;  // 202752 B
  cudaFuncSetAttribute(gemm_kernel,
                       cudaFuncAttributeMaxDynamicSharedMemorySize, smem);
  int mtiles = (200000 + 127) / 128;  // 1563
  gemm_kernel<<<mtiles, 256, smem>>>(zp, zo, w1);

  int nwarps = 3 * EE;                      // 1.5M edges, 1 warp each
  int nblocks = (nwarps * 32 + 255) / 256;  // 187500
  edge_kernel<<<nblocks, 256>>>(e0, e1, e2, b1, w2, b2, (float*)d_out);
}

// round 4
// speedup vs baseline: 2.9708x; 1.4807x over previous
#include <cuda_runtime.h>
#include <cuda_fp16.h>
#include <cstdint>
#include <cstddef>

#define NN 100000
#define EE 500000

// Per-node first-layer tables in fp16 (102.4 MB total -> L2-resident).
// P[n, 0:128] = z_pnode[n] @ w1_top
// P[n, 128:256] = z_pnode[n] @ w1_bot + b1   (b1 folded in)
__device__ __half g_P[(size_t)NN * 256];
__device__ __half g_O[(size_t)NN * 256];
// w1 pre-converted to tf32, laid out as [k][nn] (k=0..127, nn=0..255):
// nn<128 -> w1_top col nn ; nn>=128 -> w1_bot col nn-128
__device__ float g_w1t[128 * 256];

__device__ __forceinline__ uint32_t f2tf32(float f) {
  uint32_t r;
  asm("cvt.rna.tf32.f32 %0, %1;" : "=r"(r) : "f"(f));
  return r;
}

__device__ __forceinline__ void mma_tf32(float* d, const uint32_t* a,
                                         const uint32_t* b) {
  asm volatile(
      "mma.sync.aligned.m16n8k8.row.col.f32.tf32.tf32.f32 "
      "{%0,%1,%2,%3}, {%4,%5,%6,%7}, {%8,%9}, {%0,%1,%2,%3};"
      : "+f"(d[0]), "+f"(d[1]), "+f"(d[2]), "+f"(d[3])
      : "r"(a[0]), "r"(a[1]), "r"(a[2]), "r"(a[3]), "r"(b[0]), "r"(b[1]));
}

// ---------------------------------------------------------------------------
// One-shot w1 -> tf32 conversion into the GEMM's B layout.
// ---------------------------------------------------------------------------
__global__ void w1conv_kernel(const float* __restrict__ w1) {
  int idx = blockIdx.x * 256 + threadIdx.x;  // 0..32767
  int r = idx >> 7;                          // w1 row 0..255
  int c = idx & 127;                         // w1 col 0..127
  int k = r & 127;
  int nn = ((r >> 7) << 7) + c;
  g_w1t[k * 256 + nn] = __uint_as_float(f2tf32(w1[idx]));
}

#define AS_LD 132  // stride%32==4 -> conflict-free A frag loads
#define BS_LD 264  // stride%32==8 -> conflict-free B frag loads

// ---------------------------------------------------------------------------
// tf32 tensor-core GEMM: C[200000, 256] = Z[200000,128] @ [w1_top | w1_bot]
// One CTA: 128 rows x 256 cols, K=128. 8 warps, each 64x64.
// ---------------------------------------------------------------------------
__global__ void __launch_bounds__(256, 1) gemm_kernel(
    const float* __restrict__ zp, const float* __restrict__ zo,
    const float* __restrict__ b1) {
  extern __shared__ float sm[];
  float* As = sm;                // [128][AS_LD]
  float* Bs = sm + 128 * AS_LD;  // [128][BS_LD]
  const int tid = threadIdx.x;
  const int row0 = blockIdx.x * 128;

  // Copy pre-converted B tile (128 x 256) into padded smem.
  {
    const float4* w4 = (const float4*)g_w1t;
#pragma unroll
    for (int i = 0; i < 32; i++) {
      int slot = tid + 256 * i;  // 8192 float4 slots (128 rows x 64 float4)
      int r = slot >> 6;
      int c4 = slot & 63;
      ((float4*)(Bs + r * BS_LD))[c4] = w4[slot];
    }
  }
  // Load A tile (128 rows x 128 k) with p/o straddle, clamped last tile.
#pragma unroll
  for (int i = 0; i < 16; i++) {
    int slot = tid + 256 * i;  // 4096 float4 slots
    int r = slot >> 5;
    int c4 = slot & 31;
    int grow = row0 + r;
    if (grow > 199999) grow = 199999;
    const float* src = (grow < NN) ? (zp + (size_t)grow * 128)
                                   : (zo + (size_t)(grow - NN) * 128);
    float4 v = ((const float4*)src)[c4];
    float* dst = As + r * AS_LD + c4 * 4;
    dst[0] = __uint_as_float(f2tf32(v.x));
    dst[1] = __uint_as_float(f2tf32(v.y));
    dst[2] = __uint_as_float(f2tf32(v.z));
    dst[3] = __uint_as_float(f2tf32(v.w));
  }
  __syncthreads();

  const int lane = tid & 31;
  const int wid = tid >> 5;
  const int g = lane >> 2;  // group id (0..7)
  const int tg = lane & 3;  // thread in group (0..3)
  const int wm = wid & 1;   // warp M (2)
  const int wn = wid >> 1;  // warp N (4)
  const int arow = wm * 64;
  const int bcol = wn * 64;

  float acc[4][8][4];
#pragma unroll
  for (int mi = 0; mi < 4; mi++)
#pragma unroll
    for (int ni = 0; ni < 8; ni++)
#pragma unroll
      for (int q = 0; q < 4; q++) acc[mi][ni][q] = 0.f;

#pragma unroll
  for (int k0 = 0; k0 < 128; k0 += 8) {
    uint32_t bf[8][2];
#pragma unroll
    for (int ni = 0; ni < 8; ni++) {
      int col = bcol + ni * 8 + g;
      bf[ni][0] = __float_as_uint(Bs[(k0 + tg) * BS_LD + col]);
      bf[ni][1] = __float_as_uint(Bs[(k0 + 4 + tg) * BS_LD + col]);
    }
#pragma unroll
    for (int mi = 0; mi < 4; mi++) {
      int rb = arow + mi * 16 + g;
      uint32_t af[4];
      af[0] = __float_as_uint(As[rb * AS_LD + k0 + tg]);
      af[1] = __float_as_uint(As[(rb + 8) * AS_LD + k0 + tg]);
      af[2] = __float_as_uint(As[rb * AS_LD + k0 + 4 + tg]);
      af[3] = __float_as_uint(As[(rb + 8) * AS_LD + k0 + 4 + tg]);
#pragma unroll
      for (int ni = 0; ni < 8; ni++) mma_tf32(acc[mi][ni], af, bf[ni]);
    }
  }

  // Store C as fp16 table rows; fold b1 into bot-half (cols >= 128).
  const bool bot = (bcol >= 128);
#pragma unroll
  for (int mi = 0; mi < 4; mi++) {
    int r0 = row0 + wm * 64 + mi * 16 + g;
#pragma unroll
    for (int half = 0; half < 2; half++) {
      int grow = r0 + half * 8;
      if (grow >= 200000) continue;
      __half* tab = (grow < NN) ? (g_P + (size_t)grow * 256)
                                : (g_O + (size_t)(grow - NN) * 256);
#pragma unroll
      for (int ni = 0; ni < 8; ni++) {
        int c = bcol + ni * 8 + tg * 2;
        float v0 = acc[mi][ni][half * 2];
        float v1 = acc[mi][ni][half * 2 + 1];
        if (bot) {
          float2 bb = *(const float2*)(b1 + (c - 128));
          v0 += bb.x;
          v1 += bb.y;
        }
        *(__half2*)(tab + c) = __floats2half2_rn(v0, v1);
      }
    }
  }
}

// ---------------------------------------------------------------------------
// Edge pass v2: persistent warps, 2 edges per warp-iteration (16-lane halves),
// uint4 (8-feature) gathers, w2/b2 in registers, b1 pre-folded into tables.
// out[e] = relu(tabS[src, 0:128] + tabD[dst, 128:256]) . w2 + b2
// ---------------------------------------------------------------------------
#define NPAIRS (3 * EE / 2)  // 750000
__global__ void __launch_bounds__(256) edge_kernel(
    const int* __restrict__ e0, const int* __restrict__ e1,
    const int* __restrict__ e2, const float* __restrict__ w2,
    const float* __restrict__ b2, float* __restrict__ out) {
  const int lane = threadIdx.x & 31;
  const int h = lane >> 4;   // half-warp id (0/1)
  const int l = lane & 15;   // lane within half
  const int warpId = (blockIdx.x * 256 + threadIdx.x) >> 5;
  const int W = gridDim.x * 8;  // total warps

  // Per-lane second-layer weights: features l*8 .. l*8+7
  const float4 wa = ((const float4*)w2)[l * 2];
  const float4 wb = ((const float4*)w2)[l * 2 + 1];
  const float b2v = b2[0];

#pragma unroll 2
  for (int p = warpId; p < NPAIRS; p += W) {
    int e = 2 * p + h;  // this half-warp's edge
    int t = (e >= EE) + (e >= 2 * EE);
    int ei = e - t * EE;
    const int* idx = (t == 0) ? e0 : (t == 1) ? e1 : e2;
    int s = idx[ei];
    int d = idx[EE + ei];
    const __half* srow = ((t == 0) ? g_P : g_O) + (unsigned)s * 256u;
    const __half* drow = ((t == 1) ? g_P : g_O) + (unsigned)d * 256u + 128u;

    uint4 sa = ((const uint4*)srow)[l];
    uint4 da = ((const uint4*)drow)[l];

    float acc;
    {
      float2 sx = __half22float2(*(const __half2*)&sa.x);
      float2 dx = __half22float2(*(const __half2*)&da.x);
      float2 sy = __half22float2(*(const __half2*)&sa.y);
      float2 dy = __half22float2(*(const __half2*)&da.y);
      float h0 = fmaxf(sx.x + dx.x, 0.f);
      float h1 = fmaxf(sx.y + dx.y, 0.f);
      float h2 = fmaxf(sy.x + dy.x, 0.f);
      float h3 = fmaxf(sy.y + dy.y, 0.f);
      acc = h0 * wa.x + h1 * wa.y + h2 * wa.z + h3 * wa.w;
    }
    {
      float2 sx = __half22float2(*(const __half2*)&sa.z);
      float2 dx = __half22float2(*(const __half2*)&da.z);
      float2 sy = __half22float2(*(const __half2*)&sa.w);
      float2 dy = __half22float2(*(const __half2*)&da.w);
      float h0 = fmaxf(sx.x + dx.x, 0.f);
      float h1 = fmaxf(sx.y + dx.y, 0.f);
      float h2 = fmaxf(sy.x + dy.x, 0.f);
      float h3 = fmaxf(sy.y + dy.y, 0.f);
      acc += h0 * wb.x + h1 * wb.y + h2 * wb.z + h3 * wb.w;
    }
    // Reduce within the 16-lane half-warp.
#pragma unroll
    for (int o = 8; o; o >>= 1) acc += __shfl_xor_sync(0xffffffffu, acc, o);
    if (l == 0) out[e] = acc + b2v;
  }
}

extern "C" void kernel_launch(void* const* d_in, const int* in_sizes, int n_in,
                              void* d_out, int out_size) {
  const float* zp = (const float*)d_in[0];
  const float* zo = (const float*)d_in[1];
  const int* e0 = (const int*)d_in[2];
  const int* e1 = (const int*)d_in[3];
  const int* e2 = (const int*)d_in[4];
  const float* w1 = (const float*)d_in[5];
  const float* b1 = (const float*)d_in[6];
  const float* w2 = (const float*)d_in[7];
  const float* b2 = (const float*)d_in[8];

  w1conv_kernel<<<128, 256>>>(w1);

  const int smem = (128 * AS_LD + 128 * BS_LD) * 4;  // 202752 B
  cudaFuncSetAttribute(gemm_kernel,
                       cudaFuncAttributeMaxDynamicSharedMemorySize, smem);
  int mtiles = (200000 + 127) / 128;  // 1563
  gemm_kernel<<<mtiles, 256, smem>>>(zp, zo, b1);

  edge_kernel<<<148 * 8, 256>>>(e0, e1, e2, w2, b2, (float*)d_out);
}

// round 5
// speedup vs baseline: 3.6398x; 1.2252x over previous
#include <cuda_runtime.h>
#include <cuda_fp16.h>
#include <cstdint>
#include <cstddef>

#define NN 100000
#define EE 500000
#define MROWS 200000
#define MTILES 1563             // ceil(200000/128)
#define MROWS_PAD (MTILES * 128)

// Per-node first-layer tables in fp16 (102.4 MB -> mostly L2-resident).
// P[n, 0:128] = z_pnode[n] @ w1_top ; P[n, 128:256] = z_pnode[n] @ w1_bot + b1
__device__ __half g_P[(size_t)NN * 256];
__device__ __half g_O[(size_t)NN * 256];
// w1 in fp16, [kpair 0..63][nn 0..255], half2 = (w1t[2p][nn], w1t[2p+1][nn])
__device__ __half2 g_w1h[64 * 256];
// z (concat pnode,onode) in fp16 row-major, padded to tile multiple.
__device__ __half g_Zh[(size_t)MROWS_PAD * 128];

__device__ __forceinline__ void mma_f16(float* d, const uint32_t* a,
                                        const uint32_t* b) {
  asm volatile(
      "mma.sync.aligned.m16n8k16.row.col.f32.f16.f16.f32 "
      "{%0,%1,%2,%3}, {%4,%5,%6,%7}, {%8,%9}, {%0,%1,%2,%3};"
      : "+f"(d[0]), "+f"(d[1]), "+f"(d[2]), "+f"(d[3])
      : "r"(a[0]), "r"(a[1]), "r"(a[2]), "r"(a[3]), "r"(b[0]), "r"(b[1]));
}

__device__ __forceinline__ void cp16(void* smem_dst, const void* gmem_src) {
  uint32_t s = (uint32_t)__cvta_generic_to_shared(smem_dst);
  asm volatile("cp.async.cg.shared.global [%0], [%1], 16;" ::"r"(s),
               "l"(gmem_src));
}

// ---------------------------------------------------------------------------
// One-shot conversions.
// ---------------------------------------------------------------------------
__global__ void w1conv_kernel(const float* __restrict__ w1) {
  int idx = blockIdx.x * 256 + threadIdx.x;  // 0..16383 = (p, nn)
  int p = idx >> 8;
  int nn = idx & 255;
  int off = (nn >> 7) << 7;  // 0 (top) or 128 (bot)
  int c = nn & 127;
  float lo = w1[(2 * p + off) * 128 + c];
  float hi = w1[(2 * p + 1 + off) * 128 + c];
  g_w1h[p * 256 + nn] = __floats2half2_rn(lo, hi);
}

__global__ void zconv_kernel(const float* __restrict__ zp,
                             const float* __restrict__ zo) {
  int i = blockIdx.x * 256 + threadIdx.x;  // float4 slot, 0..6399999
  const int ZP4 = NN * 32;                 // float4 count in zp
  const float4* src =
      (i < ZP4) ? ((const float4*)zp + i) : ((const float4*)zo + (i - ZP4));
  float4 v = *src;
  __half2* dst = (__half2*)g_Zh + (size_t)i * 2;
  dst[0] = __floats2half2_rn(v.x, v.y);
  dst[1] = __floats2half2_rn(v.z, v.w);
}

#define BS_LD2 264  // half2 per B pair-row (1056B; %128==32 -> conflict-free)
#define AS_LDH 136  // halfs per A row (272B; %128==16 -> conflict-free)
#define B_BYTES (64 * BS_LD2 * 4)        // 67584
#define A_BYTES (128 * AS_LDH * 2)       // 34816 per buffer
#define SMEM_TOTAL (B_BYTES + 2 * A_BYTES)

// ---------------------------------------------------------------------------
// Persistent fp16 GEMM: C[200000,256] = Zh @ [w1_top | w1_bot] (+b1 on bot).
// 148 CTAs, each loops M-tiles with cp.async double-buffered A; B resident.
// 8 warps, each 64x64 of the 128x256 tile.
// ---------------------------------------------------------------------------
__global__ void __launch_bounds__(256, 1) gemm_kernel(
    const float* __restrict__ b1) {
  extern __shared__ char smem_raw[];
  __half2* Bsh = (__half2*)smem_raw;              // [64][BS_LD2]
  char* Abase = smem_raw + B_BYTES;               // 2 x [128][AS_LDH] halfs
  const int tid = threadIdx.x;

  // Load B once (4096 uint4 = 16 per thread).
  {
    const uint4* src = (const uint4*)g_w1h;
#pragma unroll
    for (int i = 0; i < 16; i++) {
      int slot = tid + 256 * i;
      int r = slot >> 6;
      int c4 = slot & 63;
      *(uint4*)((char*)Bsh + r * (BS_LD2 * 4) + c4 * 16) = src[slot];
    }
  }

  const int lane = tid & 31;
  const int wid = tid >> 5;
  const int g = lane >> 2;
  const int tg = lane & 3;
  const int wm = wid & 1;
  const int wn = wid >> 1;
  const int arow = wm * 64;
  const int bcol = wn * 64;
  const bool bot = (bcol >= 128);

  // A tile async load: 2048 x 16B chunks, 8 per thread.
  auto issueA = [&](int tile, int buf) {
    const __half* src = g_Zh + (size_t)tile * (128 * 128);
    char* dst = Abase + buf * A_BYTES;
#pragma unroll
    for (int j = 0; j < 8; j++) {
      int s = tid + 256 * j;
      int r = s >> 4;
      int c16 = s & 15;
      cp16(dst + r * (AS_LDH * 2) + c16 * 16, src + r * 128 + c16 * 8);
    }
  };

  int t = blockIdx.x;
  if (t >= MTILES) return;
  issueA(t, 0);
  asm volatile("cp.async.commit_group;" ::: "memory");
  int buf = 0;

  while (true) {
    int tn = t + gridDim.x;
    bool more = (tn < MTILES);
    if (more) issueA(tn, buf ^ 1);
    asm volatile("cp.async.commit_group;" ::: "memory");
    asm volatile("cp.async.wait_group 1;" ::: "memory");
    __syncthreads();

    const __half* A = (const __half*)(Abase + buf * A_BYTES);
    float acc[4][8][4];
#pragma unroll
    for (int mi = 0; mi < 4; mi++)
#pragma unroll
      for (int ni = 0; ni < 8; ni++)
#pragma unroll
        for (int q = 0; q < 4; q++) acc[mi][ni][q] = 0.f;

#pragma unroll
    for (int k0 = 0; k0 < 128; k0 += 16) {
      int hp = k0 >> 1;  // B pair-row base
      uint32_t bf[8][2];
#pragma unroll
      for (int ni = 0; ni < 8; ni++) {
        int col = bcol + ni * 8 + g;
        bf[ni][0] = *(const uint32_t*)&Bsh[(hp + tg) * BS_LD2 + col];
        bf[ni][1] = *(const uint32_t*)&Bsh[(hp + 4 + tg) * BS_LD2 + col];
      }
#pragma unroll
      for (int mi = 0; mi < 4; mi++) {
        int rb = arow + mi * 16 + g;
        uint32_t af[4];
        af[0] = *(const uint32_t*)&A[rb * AS_LDH + k0 + 2 * tg];
        af[1] = *(const uint32_t*)&A[(rb + 8) * AS_LDH + k0 + 2 * tg];
        af[2] = *(const uint32_t*)&A[rb * AS_LDH + k0 + 8 + 2 * tg];
        af[3] = *(const uint32_t*)&A[(rb + 8) * AS_LDH + k0 + 8 + 2 * tg];
#pragma unroll
        for (int ni = 0; ni < 8; ni++) mma_f16(acc[mi][ni], af, bf[ni]);
      }
    }

    // Epilogue: fold b1 into bot half, store fp16 table rows.
    int row0 = t * 128;
#pragma unroll
    for (int mi = 0; mi < 4; mi++) {
      int r0 = row0 + wm * 64 + mi * 16 + g;
#pragma unroll
      for (int half = 0; half < 2; half++) {
        int grow = r0 + half * 8;
        if (grow >= MROWS) continue;
        __half* tab = (grow < NN) ? (g_P + (size_t)grow * 256)
                                  : (g_O + (size_t)(grow - NN) * 256);
#pragma unroll
        for (int ni = 0; ni < 8; ni++) {
          int c = bcol + ni * 8 + tg * 2;
          float v0 = acc[mi][ni][half * 2];
          float v1 = acc[mi][ni][half * 2 + 1];
          if (bot) {
            float2 bb = *(const float2*)(b1 + (c - 128));
            v0 += bb.x;
            v1 += bb.y;
          }
          *(__half2*)(tab + c) = __floats2half2_rn(v0, v1);
        }
      }
    }
    __syncthreads();
    if (!more) break;
    t = tn;
    buf ^= 1;
  }
}

// ---------------------------------------------------------------------------
// Edge pass: persistent warps, 2 edges per warp-iteration (16-lane halves).
// out[e] = relu(tabS[src, 0:128] + tabD[dst, 128:256]) . w2 + b2
// ---------------------------------------------------------------------------
#define NPAIRS (3 * EE / 2)  // 750000
__global__ void __launch_bounds__(256) edge_kernel(
    const int* __restrict__ e0, const int* __restrict__ e1,
    const int* __restrict__ e2, const float* __restrict__ w2,
    const float* __restrict__ b2, float* __restrict__ out) {
  const int lane = threadIdx.x & 31;
  const int h = lane >> 4;
  const int l = lane & 15;
  const int warpId = (blockIdx.x * 256 + threadIdx.x) >> 5;
  const int W = gridDim.x * 8;

  const float4 wa = ((const float4*)w2)[l * 2];
  const float4 wb = ((const float4*)w2)[l * 2 + 1];
  const float b2v = b2[0];

#pragma unroll 2
  for (int p = warpId; p < NPAIRS; p += W) {
    int e = 2 * p + h;
    int t = (e >= EE) + (e >= 2 * EE);
    int ei = e - t * EE;
    const int* idx = (t == 0) ? e0 : (t == 1) ? e1 : e2;
    int s = idx[ei];
    int d = idx[EE + ei];
    const __half* srow = ((t == 0) ? g_P : g_O) + (unsigned)s * 256u;
    const __half* drow = ((t == 1) ? g_P : g_O) + (unsigned)d * 256u + 128u;

    uint4 sa = ((const uint4*)srow)[l];
    uint4 da = ((const uint4*)drow)[l];

    float acc;
    {
      float2 sx = __half22float2(*(const __half2*)&sa.x);
      float2 dx = __half22float2(*(const __half2*)&da.x);
      float2 sy = __half22float2(*(const __half2*)&sa.y);
      float2 dy = __half22float2(*(const __half2*)&da.y);
      float h0 = fmaxf(sx.x + dx.x, 0.f);
      float h1 = fmaxf(sx.y + dx.y, 0.f);
      float h2 = fmaxf(sy.x + dy.x, 0.f);
      float h3 = fmaxf(sy.y + dy.y, 0.f);
      acc = h0 * wa.x + h1 * wa.y + h2 * wa.z + h3 * wa.w;
    }
    {
      float2 sx = __half22float2(*(const __half2*)&sa.z);
      float2 dx = __half22float2(*(const __half2*)&da.z);
      float2 sy = __half22float2(*(const __half2*)&sa.w);
      float2 dy = __half22float2(*(const __half2*)&da.w);
      float h0 = fmaxf(sx.x + dx.x, 0.f);
      float h1 = fmaxf(sx.y + dx.y, 0.f);
      float h2 = fmaxf(sy.x + dy.x, 0.f);
      float h3 = fmaxf(sy.y + dy.y, 0.f);
      acc += h0 * wb.x + h1 * wb.y + h2 * wb.z + h3 * wb.w;
    }
#pragma unroll
    for (int o = 8; o; o >>= 1) acc += __shfl_xor_sync(0xffffffffu, acc, o);
    if (l == 0) out[e] = acc + b2v;
  }
}

extern "C" void kernel_launch(void* const* d_in, const int* in_sizes, int n_in,
                              void* d_out, int out_size) {
  const float* zp = (const float*)d_in[0];
  const float* zo = (const float*)d_in[1];
  const int* e0 = (const int*)d_in[2];
  const int* e1 = (const int*)d_in[3];
  const int* e2 = (const int*)d_in[4];
  const float* w1 = (const float*)d_in[5];
  const float* b1 = (const float*)d_in[6];
  const float* w2 = (const float*)d_in[7];
  const float* b2 = (const float*)d_in[8];

  w1conv_kernel<<<64, 256>>>(w1);
  zconv_kernel<<<(MROWS * 32) / 256, 256>>>(zp, zo);  // 25000 blocks

  cudaFuncSetAttribute(gemm_kernel,
                       cudaFuncAttributeMaxDynamicSharedMemorySize, SMEM_TOTAL);
  gemm_kernel<<<148, 256, SMEM_TOTAL>>>(b1);

  edge_kernel<<<148 * 8, 256>>>(e0, e1, e2, w2, b2, (float*)d_out);
}

// round 6
// speedup vs baseline: 4.4510x; 1.2229x over previous
#include <cuda_runtime.h>
#include <cuda_fp16.h>
#include <cstdint>
#include <cstddef>

#define NN 100000
#define EE 500000
#define MROWS 200000
#define MTILES 1563  // ceil(200000/128)

// Per-node first-layer tables in fp16 (102.4 MB -> mostly L2-resident).
// P[n, 0:128] = z_pnode[n] @ w1_top ; P[n, 128:256] = z_pnode[n] @ w1_bot + b1
__device__ __half g_P[(size_t)NN * 256];
__device__ __half g_O[(size_t)NN * 256];

__device__ __forceinline__ void mma_f16(float* d, const uint32_t* a,
                                        const uint32_t* b) {
  asm volatile(
      "mma.sync.aligned.m16n8k16.row.col.f32.f16.f16.f32 "
      "{%0,%1,%2,%3}, {%4,%5,%6,%7}, {%8,%9}, {%0,%1,%2,%3};"
      : "+f"(d[0]), "+f"(d[1]), "+f"(d[2]), "+f"(d[3])
      : "r"(a[0]), "r"(a[1]), "r"(a[2]), "r"(a[3]), "r"(b[0]), "r"(b[1]));
}

__device__ __forceinline__ void cp16(void* smem_dst, const void* gmem_src) {
  uint32_t s = (uint32_t)__cvta_generic_to_shared(smem_dst);
  asm volatile("cp.async.cg.shared.global [%0], [%1], 16;" ::"r"(s),
               "l"(gmem_src));
}

__device__ __forceinline__ uint32_t pack_h2(float lo, float hi) {
  __half2 h = __floats2half2_rn(lo, hi);
  return *(uint32_t*)&h;
}

#define BS_LD2 264  // half2 per B pair-row (1056B; %128==32 -> conflict-free)
#define AS_LDF 132  // fp32 per A row (528B; words%32==4 -> conflict-free)
#define CS_LDH 264  // halves per staged C row (528B) == A row bytes
#define B_BYTES (64 * BS_LD2 * 4)   // 67584
#define A_BYTES (128 * AS_LDF * 4)  // 67584 (== 128*CS_LDH*2)
#define SMEM_TOTAL (B_BYTES + 2 * A_BYTES)  // 202752

// ---------------------------------------------------------------------------
// Fused persistent fp16 GEMM: C[200000,256] = Z @ [w1_top | w1_bot] (+b1 bot).
// Reads fp32 z/w1 directly; converts in-kernel. 148 CTAs loop M-tiles with
// cp.async double-buffered fp32 A; B (fp16) resident; C staged in smem for
// coalesced row stores. 8 warps, each 64x64 of the 128x256 tile.
// ---------------------------------------------------------------------------
__global__ void __launch_bounds__(256, 1) gemm_kernel(
    const float* __restrict__ zp, const float* __restrict__ zo,
    const float* __restrict__ w1, const float* __restrict__ b1) {
  extern __shared__ char smem_raw[];
  __half2* Bsh = (__half2*)smem_raw;  // [64 pair-rows][BS_LD2]
  char* Abase = smem_raw + B_BYTES;   // 2 x (A fp32 tile | C half stage)
  const int tid = threadIdx.x;

  // A tile async load: 4096 x 16B fp32 chunks, 16 per thread.
  auto issueA = [&](int tile, int buf) {
    char* dst = Abase + buf * A_BYTES;
    int row0 = tile * 128;
#pragma unroll
    for (int j = 0; j < 16; j++) {
      int s = tid + 256 * j;
      int r = s >> 5;
      int c4 = s & 31;
      int grow = row0 + r;
      if (grow > MROWS - 1) grow = MROWS - 1;
      const float* src = (grow < NN) ? (zp + (size_t)grow * 128)
                                     : (zo + (size_t)(grow - NN) * 128);
      cp16(dst + r * (AS_LDF * 4) + c4 * 16, src + c4 * 4);
    }
  };

  int t = blockIdx.x;
  issueA(t, 0);
  asm volatile("cp.async.commit_group;" ::: "memory");

  // One-time B fill: fp32 w1 -> fp16 [pair p][nn] half2=(w1t[2p][nn],w1t[2p+1][nn])
  {
    const float4* w4 = (const float4*)w1;
#pragma unroll
    for (int j = 0; j < 16; j++) {
      int slot = tid + 256 * j;  // 4096 slots
      int c4 = slot & 31;
      int p = (slot >> 5) & 63;
      int hh = slot >> 11;  // 0: top cols, 1: bot cols
      float4 fa = w4[(2 * p + hh * 128) * 32 + c4];
      float4 fb = w4[(2 * p + 1 + hh * 128) * 32 + c4];
      uint4 v;
      v.x = pack_h2(fa.x, fb.x);
      v.y = pack_h2(fa.y, fb.y);
      v.z = pack_h2(fa.z, fb.z);
      v.w = pack_h2(fa.w, fb.w);
      *(uint4*)((char*)Bsh + p * (BS_LD2 * 4) + (hh * 128 + c4 * 4) * 4) = v;
    }
  }

  const int lane = tid & 31;
  const int wid = tid >> 5;
  const int g = lane >> 2;
  const int tg = lane & 3;
  const int wm = wid & 1;
  const int wn = wid >> 1;
  const int arow = wm * 64;
  const int bcol = wn * 64;
  const bool bot = (bcol >= 128);
  int buf = 0;

  while (true) {
    int tn = t + gridDim.x;
    bool more = (tn < MTILES);
    if (more) issueA(tn, buf ^ 1);
    asm volatile("cp.async.commit_group;" ::: "memory");
    asm volatile("cp.async.wait_group 1;" ::: "memory");
    __syncthreads();

    const float* A = (const float*)(Abase + buf * A_BYTES);
    float acc[4][8][4];
#pragma unroll
    for (int mi = 0; mi < 4; mi++)
#pragma unroll
      for (int ni = 0; ni < 8; ni++)
#pragma unroll
        for (int q = 0; q < 4; q++) acc[mi][ni][q] = 0.f;

#pragma unroll
    for (int k0 = 0; k0 < 128; k0 += 16) {
      int hp = k0 >> 1;
      uint32_t bf[8][2];
#pragma unroll
      for (int ni = 0; ni < 8; ni++) {
        int col = bcol + ni * 8 + g;
        bf[ni][0] = *(const uint32_t*)&Bsh[(hp + tg) * BS_LD2 + col];
        bf[ni][1] = *(const uint32_t*)&Bsh[(hp + 4 + tg) * BS_LD2 + col];
      }
#pragma unroll
      for (int mi = 0; mi < 4; mi++) {
        int rb = arow + mi * 16 + g;
        uint32_t af[4];
        {
          float2 v = *(const float2*)&A[rb * AS_LDF + k0 + 2 * tg];
          af[0] = pack_h2(v.x, v.y);
        }
        {
          float2 v = *(const float2*)&A[(rb + 8) * AS_LDF + k0 + 2 * tg];
          af[1] = pack_h2(v.x, v.y);
        }
        {
          float2 v = *(const float2*)&A[rb * AS_LDF + k0 + 8 + 2 * tg];
          af[2] = pack_h2(v.x, v.y);
        }
        {
          float2 v = *(const float2*)&A[(rb + 8) * AS_LDF + k0 + 8 + 2 * tg];
          af[3] = pack_h2(v.x, v.y);
        }
#pragma unroll
        for (int ni = 0; ni < 8; ni++) mma_f16(acc[mi][ni], af, bf[ni]);
      }
    }

    // Stage C into this A buffer (fully consumed), padded rows, then
    // write out coalesced full rows.
    __syncthreads();
    __half* Cs = (__half*)(Abase + buf * A_BYTES);
#pragma unroll
    for (int mi = 0; mi < 4; mi++) {
#pragma unroll
      for (int hf = 0; hf < 2; hf++) {
        int r = wm * 64 + mi * 16 + hf * 8 + g;
#pragma unroll
        for (int ni = 0; ni < 8; ni++) {
          int c = bcol + ni * 8 + tg * 2;
          float v0 = acc[mi][ni][hf * 2];
          float v1 = acc[mi][ni][hf * 2 + 1];
          if (bot) {
            float2 bb = *(const float2*)(b1 + (c - 128));
            v0 += bb.x;
            v1 += bb.y;
          }
          *(__half2*)(Cs + r * CS_LDH + c) = __floats2half2_rn(v0, v1);
        }
      }
    }
    __syncthreads();
    int row0 = t * 128;
#pragma unroll
    for (int j = 0; j < 16; j++) {
      int slot = tid + 256 * j;  // 128 rows x 32 uint4
      int r = slot >> 5;
      int c4 = slot & 31;
      int grow = row0 + r;
      if (grow < MROWS) {
        uint4 v = *(const uint4*)(Cs + r * CS_LDH + c4 * 8);
        __half* tab = (grow < NN) ? (g_P + (size_t)grow * 256)
                                  : (g_O + (size_t)(grow - NN) * 256);
        *(uint4*)(tab + c4 * 8) = v;
      }
    }
    __syncthreads();
    if (!more) break;
    t = tn;
    buf ^= 1;
  }
}

// ---------------------------------------------------------------------------
// Edge pass: persistent warps, 2 edges per warp-iteration (16-lane halves),
// half2 math. out[e] = relu(tabS[src,0:128] + tabD[dst,128:256]) . w2 + b2
// ---------------------------------------------------------------------------
#define NPAIRS (3 * EE / 2)  // 750000
__global__ void __launch_bounds__(256) edge_kernel(
    const int* __restrict__ e0, const int* __restrict__ e1,
    const int* __restrict__ e2, const float* __restrict__ w2,
    const float* __restrict__ b2, float* __restrict__ out) {
  const int lane = threadIdx.x & 31;
  const int h = lane >> 4;
  const int l = lane & 15;
  const int warpId = (blockIdx.x * 256 + threadIdx.x) >> 5;
  const int W = gridDim.x * 8;

  // Per-lane second-layer weights (features l*8 .. l*8+7) in half2.
  const float4 wa = ((const float4*)w2)[l * 2];
  const float4 wb = ((const float4*)w2)[l * 2 + 1];
  const __half2 w01 = __floats2half2_rn(wa.x, wa.y);
  const __half2 w23 = __floats2half2_rn(wa.z, wa.w);
  const __half2 w45 = __floats2half2_rn(wb.x, wb.y);
  const __half2 w67 = __floats2half2_rn(wb.z, wb.w);
  const __half2 z2 = __float2half2_rn(0.f);
  const float b2v = b2[0];

#pragma unroll 2
  for (int p = warpId; p < NPAIRS; p += W) {
    int e = 2 * p + h;
    int t = (e >= EE) + (e >= 2 * EE);
    int ei = e - t * EE;
    const int* idx = (t == 0) ? e0 : (t == 1) ? e1 : e2;
    int s = idx[ei];
    int d = idx[EE + ei];
    const __half* srow = ((t == 0) ? g_P : g_O) + (unsigned)s * 256u;
    const __half* drow = ((t == 1) ? g_P : g_O) + (unsigned)d * 256u + 128u;

    uint4 sa = ((const uint4*)srow)[l];
    uint4 da = ((const uint4*)drow)[l];

    __half2 h0 = __hmax2(__hadd2(*(__half2*)&sa.x, *(__half2*)&da.x), z2);
    __half2 h1 = __hmax2(__hadd2(*(__half2*)&sa.y, *(__half2*)&da.y), z2);
    __half2 h2 = __hmax2(__hadd2(*(__half2*)&sa.z, *(__half2*)&da.z), z2);
    __half2 h3 = __hmax2(__hadd2(*(__half2*)&sa.w, *(__half2*)&da.w), z2);
    __half2 pa = __hfma2(h1, w23, __hmul2(h0, w01));
    __half2 pb = __hfma2(h3, w67, __hmul2(h2, w45));
    float2 fa = __half22float2(pa);
    float2 fb = __half22float2(pb);
    float acc = (fa.x + fa.y) + (fb.x + fb.y);
#pragma unroll
    for (int o = 8; o; o >>= 1) acc += __shfl_xor_sync(0xffffffffu, acc, o);
    if (l == 0) out[e] = acc + b2v;
  }
}

extern "C" void kernel_launch(void* const* d_in, const int* in_sizes, int n_in,
                              void* d_out, int out_size) {
  const float* zp = (const float*)d_in[0];
  const float* zo = (const float*)d_in[1];
  const int* e0 = (const int*)d_in[2];
  const int* e1 = (const int*)d_in[3];
  const int* e2 = (const int*)d_in[4];
  const float* w1 = (const float*)d_in[5];
  const float* b1 = (const float*)d_in[6];
  const float* w2 = (const float*)d_in[7];
  const float* b2 = (const float*)d_in[8];

  cudaFuncSetAttribute(gemm_kernel,
                       cudaFuncAttributeMaxDynamicSharedMemorySize, SMEM_TOTAL);
  gemm_kernel<<<148, 256, SMEM_TOTAL>>>(zp, zo, w1, b1);

  edge_kernel<<<148 * 8, 256>>>(e0, e1, e2, w2, b2, (float*)d_out);
}